// round 1
// baseline (speedup 1.0000x reference)
#include <cuda_runtime.h>
#include <cstdint>

// ---------------------------------------------------------------------------
// Problem constants (fixed shapes for this dataset)
// ---------------------------------------------------------------------------
#define NMAX 100000
#define EMAX 1600000
#define FIN  512
#define HID  64      // 8 heads * 8
#define NH1  8
#define OC1  8
#define C2   16
#define NEG_SLOPE 0.2f
#define EPSV 1e-16f

// ---------------------------------------------------------------------------
// Device scratch (static allocation — no cudaMalloc allowed)
// ---------------------------------------------------------------------------
__device__ float g_h1[(size_t)NMAX * HID];      // layer1 pre-agg features
__device__ float g_helu[(size_t)NMAX * HID];    // elu(agg1 + bias1)
__device__ float g_y2[(size_t)NMAX * C2];       // layer2 pre-agg features
__device__ float g_as1[(size_t)NMAX * NH1];
__device__ float g_ad1[(size_t)NMAX * NH1];
__device__ float g_as2[NMAX];
__device__ float g_ad2[NMAX];
__device__ int   g_rowptr[NMAX + 1];
__device__ int   g_head[NMAX];
__device__ int   g_cnt[NMAX];
__device__ int   g_col[EMAX];
__device__ int   g_is64;

__device__ __forceinline__ float lrelu(float v) { return v > 0.f ? v : NEG_SLOPE * v; }

// packed fp32x2 fma (Blackwell)
__device__ __forceinline__ unsigned long long ffma2(unsigned long long a,
                                                    unsigned long long b,
                                                    unsigned long long c) {
    unsigned long long d;
    asm("fma.rn.f32x2 %0, %1, %2, %3;" : "=l"(d) : "l"(a), "l"(b), "l"(c));
    return d;
}
__device__ __forceinline__ unsigned long long pack2(float x) {
    unsigned long long d;
    asm("mov.b64 %0, {%1, %1};" : "=l"(d) : "f"(x));
    return d;
}
__device__ __forceinline__ void unpack2(unsigned long long v, float& lo, float& hi) {
    asm("mov.b64 {%0, %1}, %2;" : "=f"(lo), "=f"(hi) : "l"(v));
}

// ---------------------------------------------------------------------------
// edge_index dtype detection (int64 vs int32) — deterministic, data-derived
// ---------------------------------------------------------------------------
__global__ void detect_kernel(const long long* p, int N, int E) {
    if (threadIdx.x == 0 && blockIdx.x == 0) {
        int n = E < 64 ? E : 64;
        int ok = 1;
        for (int i = 0; i < n; i++) {
            long long v = p[i];
            if (v < 0 || v >= (long long)N) { ok = 0; break; }
        }
        g_is64 = ok;
    }
}

__global__ void zero_cnt_kernel(int N) {
    int i = blockIdx.x * blockDim.x + threadIdx.x;
    if (i < N) g_cnt[i] = 0;
}

__global__ void count_kernel(const void* ei, int E, int N) {
    int e = blockIdx.x * blockDim.x + threadIdx.x;
    if (e >= E) return;
    int d = g_is64 ? (int)((const long long*)ei)[(size_t)E + e]
                   : ((const int*)ei)[(size_t)E + e];
    atomicAdd(&g_cnt[d], 1);
}

// single-block exclusive scan over g_cnt -> g_rowptr, also seeds g_head
__global__ void scan_kernel(int N) {
    __shared__ int warpsums[32];
    __shared__ int s_carry;
    int tid = threadIdx.x;
    if (tid == 0) s_carry = 0;
    __syncthreads();
    for (int base = 0; base < N; base += 1024) {
        int i = base + tid;
        int v = (i < N) ? g_cnt[i] : 0;
        int x = v;
        #pragma unroll
        for (int d = 1; d < 32; d <<= 1) {
            int t = __shfl_up_sync(0xffffffffu, x, d);
            if ((tid & 31) >= d) x += t;
        }
        if ((tid & 31) == 31) warpsums[tid >> 5] = x;
        __syncthreads();
        if (tid < 32) {
            int w = warpsums[tid];
            #pragma unroll
            for (int d = 1; d < 32; d <<= 1) {
                int t = __shfl_up_sync(0xffffffffu, w, d);
                if (tid >= d) w += t;
            }
            warpsums[tid] = w;
        }
        __syncthreads();
        int incl = x + ((tid >= 32) ? warpsums[(tid >> 5) - 1] : 0) + s_carry;
        int excl = incl - v;
        if (i < N) { g_rowptr[i] = excl; g_head[i] = excl; }
        __syncthreads();
        if (tid == 1023) s_carry = incl;
        __syncthreads();
    }
    if (tid == 0) g_rowptr[N] = s_carry;
}

__global__ void scatter_kernel(const void* ei, int E) {
    int e = blockIdx.x * blockDim.x + threadIdx.x;
    if (e >= E) return;
    int s, d;
    if (g_is64) {
        s = (int)((const long long*)ei)[e];
        d = (int)((const long long*)ei)[(size_t)E + e];
    } else {
        s = ((const int*)ei)[e];
        d = ((const int*)ei)[(size_t)E + e];
    }
    int p = atomicAdd(&g_head[d], 1);
    g_col[p] = s;
}

// ---------------------------------------------------------------------------
// GEMM1: h1[N,64] = x[N,512] @ W1[512,64]   (packed f32x2 FMA)
// Block: 128 rows x 64 cols, 256 threads, thread tile 8x4 (4 row-pairs x 4 cols)
// ---------------------------------------------------------------------------
#define GBM 128
#define GBK 16
__global__ __launch_bounds__(256) void gemm1_kernel(const float* __restrict__ x,
                                                    const float* __restrict__ W,
                                                    int Nn) {
    __shared__ float As[GBK][GBM + 2];   // transposed: As[k][row]
    __shared__ float Bs[GBK][HID];
    int tid = threadIdx.x;
    int tx = tid & 15;       // col group: cols tx*4 .. tx*4+3
    int ty = tid >> 4;       // row group: rows ty*8 .. ty*8+7
    int row0 = blockIdx.x * GBM;

    unsigned long long acc[4][4];
    #pragma unroll
    for (int p = 0; p < 4; p++)
        #pragma unroll
        for (int c = 0; c < 4; c++) acc[p][c] = 0ull;

    for (int k0 = 0; k0 < FIN; k0 += GBK) {
        // load A tile (128x16), 8 floats/thread as 2x float4, store transposed
        #pragma unroll
        for (int i = 0; i < 2; i++) {
            int t4 = tid + (i << 8);
            int r = t4 >> 2, kk = (t4 & 3) << 2;
            int gr = row0 + r;
            float4 v = make_float4(0.f, 0.f, 0.f, 0.f);
            if (gr < Nn) v = *(const float4*)&x[(size_t)gr * FIN + k0 + kk];
            As[kk + 0][r] = v.x; As[kk + 1][r] = v.y;
            As[kk + 2][r] = v.z; As[kk + 3][r] = v.w;
        }
        // load B tile (16x64), 4 floats/thread
        {
            int br = tid >> 4, bc = (tid & 15) << 2;
            float4 v = *(const float4*)&W[(size_t)(k0 + br) * HID + bc];
            *(float4*)&Bs[br][bc] = v;
        }
        __syncthreads();
        #pragma unroll
        for (int k = 0; k < GBK; k++) {
            unsigned long long a2[4];
            #pragma unroll
            for (int p = 0; p < 4; p++)
                a2[p] = *(const unsigned long long*)&As[k][ty * 8 + p * 2];
            float4 b = *(const float4*)&Bs[k][tx << 2];
            unsigned long long bb[4];
            bb[0] = pack2(b.x); bb[1] = pack2(b.y);
            bb[2] = pack2(b.z); bb[3] = pack2(b.w);
            #pragma unroll
            for (int p = 0; p < 4; p++)
                #pragma unroll
                for (int c = 0; c < 4; c++)
                    acc[p][c] = ffma2(a2[p], bb[c], acc[p][c]);
        }
        __syncthreads();
    }
    // epilogue
    #pragma unroll
    for (int p = 0; p < 4; p++) {
        int r0 = row0 + ty * 8 + p * 2;
        #pragma unroll
        for (int c = 0; c < 4; c++) {
            float lo, hi;
            unpack2(acc[p][c], lo, hi);
            int col = tx * 4 + c;
            if (r0 < Nn)     g_h1[(size_t)r0 * HID + col] = lo;
            if (r0 + 1 < Nn) g_h1[(size_t)(r0 + 1) * HID + col] = hi;
        }
    }
}

// ---------------------------------------------------------------------------
// attention scalars for layer 1: a_src1[n,h] = sum_c h1[n,h,c]*att_src1[h,c]
// one warp per node, lane owns components 2l, 2l+1; head = lane/4
// ---------------------------------------------------------------------------
__global__ __launch_bounds__(256) void attn1_kernel(const float* __restrict__ att_s,
                                                    const float* __restrict__ att_d,
                                                    int N) {
    int node = (blockIdx.x * blockDim.x + threadIdx.x) >> 5;
    int lane = threadIdx.x & 31;
    if (node >= N) return;
    float2 h  = *(const float2*)&g_h1[(size_t)node * HID + 2 * lane];
    float2 as = *(const float2*)&att_s[2 * lane];
    float2 ad = *(const float2*)&att_d[2 * lane];
    float ps = h.x * as.x + h.y * as.y;
    float pd = h.x * ad.x + h.y * ad.y;
    ps += __shfl_xor_sync(0xffffffffu, ps, 1);
    ps += __shfl_xor_sync(0xffffffffu, ps, 2);
    pd += __shfl_xor_sync(0xffffffffu, pd, 1);
    pd += __shfl_xor_sync(0xffffffffu, pd, 2);
    if ((lane & 3) == 0) {
        g_as1[(size_t)node * NH1 + (lane >> 2)] = ps;
        g_ad1[(size_t)node * NH1 + (lane >> 2)] = pd;
    }
}

// ---------------------------------------------------------------------------
// layer-1 segment softmax + aggregation + bias + ELU. One warp per node.
// ---------------------------------------------------------------------------
__global__ __launch_bounds__(256) void agg1_kernel(const float* __restrict__ bias1, int N) {
    int node = (blockIdx.x * blockDim.x + threadIdx.x) >> 5;
    int lane = threadIdx.x & 31;
    if (node >= N) return;
    int start = g_rowptr[node];
    int deg   = g_rowptr[node + 1] - start;

    float ad[8], asl[8];
    {
        float4 u = *(const float4*)&g_ad1[(size_t)node * NH1];
        float4 v = *(const float4*)&g_ad1[(size_t)node * NH1 + 4];
        ad[0]=u.x; ad[1]=u.y; ad[2]=u.z; ad[3]=u.w; ad[4]=v.x; ad[5]=v.y; ad[6]=v.z; ad[7]=v.w;
        float4 a = *(const float4*)&g_as1[(size_t)node * NH1];
        float4 b = *(const float4*)&g_as1[(size_t)node * NH1 + 4];
        asl[0]=a.x; asl[1]=a.y; asl[2]=a.z; asl[3]=a.w; asl[4]=b.x; asl[5]=b.y; asl[6]=b.z; asl[7]=b.w;
    }
    float selfa[8], m[8];
    #pragma unroll
    for (int h = 0; h < 8; h++) { selfa[h] = lrelu(asl[h] + ad[h]); m[h] = selfa[h]; }

    // pass 1: max
    for (int e = lane; e < deg; e += 32) {
        int j = g_col[start + e];
        float4 u = *(const float4*)&g_as1[(size_t)j * NH1];
        float4 v = *(const float4*)&g_as1[(size_t)j * NH1 + 4];
        float aj[8] = {u.x,u.y,u.z,u.w,v.x,v.y,v.z,v.w};
        #pragma unroll
        for (int h = 0; h < 8; h++) m[h] = fmaxf(m[h], lrelu(aj[h] + ad[h]));
    }
    #pragma unroll
    for (int h = 0; h < 8; h++) {
        #pragma unroll
        for (int d = 16; d >= 1; d >>= 1)
            m[h] = fmaxf(m[h], __shfl_xor_sync(0xffffffffu, m[h], d));
    }
    // pass 2: sum of exp
    float s[8] = {0,0,0,0,0,0,0,0};
    for (int e = lane; e < deg; e += 32) {
        int j = g_col[start + e];
        float4 u = *(const float4*)&g_as1[(size_t)j * NH1];
        float4 v = *(const float4*)&g_as1[(size_t)j * NH1 + 4];
        float aj[8] = {u.x,u.y,u.z,u.w,v.x,v.y,v.z,v.w};
        #pragma unroll
        for (int h = 0; h < 8; h++) s[h] += __expf(lrelu(aj[h] + ad[h]) - m[h]);
    }
    #pragma unroll
    for (int h = 0; h < 8; h++) {
        #pragma unroll
        for (int d = 16; d >= 1; d >>= 1)
            s[h] += __shfl_xor_sync(0xffffffffu, s[h], d);
        s[h] += __expf(selfa[h] - m[h]);   // self loop, added uniformly on all lanes
    }

    // pass 3: weighted accumulation; lane owns feature components 2l, 2l+1 (head = l/4)
    int hh = lane >> 2;
    float mh   = m[hh];
    float inv  = 1.f / (s[hh] + EPSV);
    float adh  = ad[hh];
    float wself = __expf(selfa[hh] - mh) * inv;
    float2 hv = *(const float2*)&g_h1[(size_t)node * HID + 2 * lane];
    float ax = wself * hv.x, ay = wself * hv.y;
    for (int e = 0; e < deg; e++) {
        int j = g_col[start + e];                 // broadcast load
        float a = lrelu(g_as1[(size_t)j * NH1 + hh] + adh);
        float w = __expf(a - mh) * inv;
        float2 v = *(const float2*)&g_h1[(size_t)j * HID + 2 * lane];
        ax = fmaf(w, v.x, ax);
        ay = fmaf(w, v.y, ay);
    }
    float2 bb = *(const float2*)&bias1[2 * lane];
    ax += bb.x; ay += bb.y;
    ax = ax > 0.f ? ax : (__expf(ax) - 1.f);
    ay = ay > 0.f ? ay : (__expf(ay) - 1.f);
    *(float2*)&g_helu[(size_t)node * HID + 2 * lane] = make_float2(ax, ay);
}

// ---------------------------------------------------------------------------
// layer-2 GEMM (thread per node): y2[N,16] = helu[N,64] @ W2[64,16]
// + attention scalars a_src2 / a_dst2
// ---------------------------------------------------------------------------
__global__ __launch_bounds__(256) void gemm2_kernel(const float* __restrict__ W2,
                                                    const float* __restrict__ att_s,
                                                    const float* __restrict__ att_d,
                                                    int N) {
    __shared__ float sW[HID * C2];
    __shared__ float sas[C2], sad[C2];
    int tid = threadIdx.x;
    for (int i = tid; i < HID * C2; i += blockDim.x) sW[i] = W2[i];
    if (tid < C2) { sas[tid] = att_s[tid]; sad[tid] = att_d[tid]; }
    __syncthreads();
    int n = blockIdx.x * blockDim.x + tid;
    if (n >= N) return;
    float acc[C2];
    #pragma unroll
    for (int c = 0; c < C2; c++) acc[c] = 0.f;
    const float* hr = &g_helu[(size_t)n * HID];
    #pragma unroll
    for (int k = 0; k < HID; k += 4) {
        float4 h4 = *(const float4*)&hr[k];
        #pragma unroll
        for (int c = 0; c < C2; c++) {
            acc[c] = fmaf(h4.x, sW[(k + 0) * C2 + c], acc[c]);
            acc[c] = fmaf(h4.y, sW[(k + 1) * C2 + c], acc[c]);
            acc[c] = fmaf(h4.z, sW[(k + 2) * C2 + c], acc[c]);
            acc[c] = fmaf(h4.w, sW[(k + 3) * C2 + c], acc[c]);
        }
    }
    #pragma unroll
    for (int c = 0; c < C2; c += 4)
        *(float4*)&g_y2[(size_t)n * C2 + c] = make_float4(acc[c], acc[c+1], acc[c+2], acc[c+3]);
    float ps = 0.f, pd = 0.f;
    #pragma unroll
    for (int c = 0; c < C2; c++) { ps = fmaf(acc[c], sas[c], ps); pd = fmaf(acc[c], sad[c], pd); }
    g_as2[n] = ps;
    g_ad2[n] = pd;
}

// ---------------------------------------------------------------------------
// layer-2 aggregation + bias + final softmax, fused output. One warp per node.
// out layout: [0, N*16)   = softmax(embeddings)
//             [N*16, 2N*16) = embeddings
// ---------------------------------------------------------------------------
__global__ __launch_bounds__(256) void agg2_kernel(const float* __restrict__ bias2,
                                                   float* __restrict__ out, int N) {
    int node = (blockIdx.x * blockDim.x + threadIdx.x) >> 5;
    int lane = threadIdx.x & 31;
    if (node >= N) return;
    int start = g_rowptr[node];
    int deg   = g_rowptr[node + 1] - start;

    float ad    = g_ad2[node];
    float selfa = lrelu(g_as2[node] + ad);
    float m = selfa;
    for (int e = lane; e < deg; e += 32)
        m = fmaxf(m, lrelu(g_as2[g_col[start + e]] + ad));
    #pragma unroll
    for (int d = 16; d >= 1; d >>= 1)
        m = fmaxf(m, __shfl_xor_sync(0xffffffffu, m, d));

    float s = 0.f;
    for (int e = lane; e < deg; e += 32)
        s += __expf(lrelu(g_as2[g_col[start + e]] + ad) - m);
    #pragma unroll
    for (int d = 16; d >= 1; d >>= 1)
        s += __shfl_xor_sync(0xffffffffu, s, d);
    float wself = __expf(selfa - m);
    s += wself;
    float inv = 1.f / (s + EPSV);

    int c = lane & 15, half = lane >> 4;
    float acc = 0.f;
    for (int e = half; e < deg; e += 2) {
        int j = g_col[start + e];
        float w = __expf(lrelu(g_as2[j] + ad) - m) * inv;
        acc = fmaf(w, g_y2[(size_t)j * C2 + c], acc);
    }
    acc += __shfl_xor_sync(0xffffffffu, acc, 16);            // combine halves
    acc = fmaf(wself * inv, g_y2[(size_t)node * C2 + c], acc); // self loop
    acc += bias2[c];                                          // embedding value

    // softmax over the 16 components (halves carry identical values)
    float mx = acc;
    #pragma unroll
    for (int d = 8; d >= 1; d >>= 1)
        mx = fmaxf(mx, __shfl_xor_sync(0xffffffffu, mx, d));
    float p = __expf(acc - mx);
    float ss = p;
    #pragma unroll
    for (int d = 8; d >= 1; d >>= 1)
        ss += __shfl_xor_sync(0xffffffffu, ss, d);
    float soft = p / ss;

    if (lane < 16) {
        out[(size_t)node * C2 + c] = soft;
        out[(size_t)N * C2 + (size_t)node * C2 + c] = acc;
    }
}

// ---------------------------------------------------------------------------
// launch
// ---------------------------------------------------------------------------
extern "C" void kernel_launch(void* const* d_in, const int* in_sizes, int n_in,
                              void* d_out, int out_size) {
    const float* x   = (const float*)d_in[0];
    const void*  ei  = d_in[1];
    const float* W1  = (const float*)d_in[2];
    const float* as1 = (const float*)d_in[3];
    const float* ad1 = (const float*)d_in[4];
    const float* b1  = (const float*)d_in[5];
    const float* W2  = (const float*)d_in[6];
    const float* as2 = (const float*)d_in[7];
    const float* ad2 = (const float*)d_in[8];
    const float* b2  = (const float*)d_in[9];
    float* out = (float*)d_out;

    int E = in_sizes[1] / 2;
    int N = in_sizes[0] / FIN;

    detect_kernel<<<1, 32>>>((const long long*)ei, N, E);
    zero_cnt_kernel<<<(N + 255) / 256, 256>>>(N);
    count_kernel<<<(E + 255) / 256, 256>>>(ei, E, N);
    scan_kernel<<<1, 1024>>>(N);
    scatter_kernel<<<(E + 255) / 256, 256>>>(ei, E);

    gemm1_kernel<<<(N + GBM - 1) / GBM, 256>>>(x, W1, N);
    attn1_kernel<<<(N + 7) / 8, 256>>>(as1, ad1, N);
    agg1_kernel<<<(N + 7) / 8, 256>>>(b1, N);
    gemm2_kernel<<<(N + 255) / 256, 256>>>(W2, as2, ad2, N);
    agg2_kernel<<<(N + 7) / 8, 256>>>(b2, out, N);
}

// round 4
// speedup vs baseline: 1.3352x; 1.3352x over previous
#include <cuda_runtime.h>
#include <cuda_bf16.h>
#include <cstdint>

// ---------------------------------------------------------------------------
// Problem constants
// ---------------------------------------------------------------------------
#define NMAX 100000
#define EMAX 1600000
#define FIN  512
#define HID  64
#define NH1  8
#define C2   16
#define NEG_SLOPE 0.2f
#define EPSV 1e-16f
#define NCHUNK 32            // K chunks of 16

// ---------------------------------------------------------------------------
// Device scratch
// ---------------------------------------------------------------------------
__device__ float g_h1[(size_t)NMAX * HID];
__device__ float g_helu[(size_t)NMAX * HID];
__device__ float g_y2[(size_t)NMAX * C2];
__device__ float g_as1[(size_t)NMAX * NH1];
__device__ float g_ad1[(size_t)NMAX * NH1];
__device__ float g_as2[NMAX];
__device__ float g_ad2[NMAX];
__device__ int   g_rowptr[NMAX + 1];
__device__ int   g_head[NMAX];
__device__ int   g_cnt[NMAX];
__device__ int   g_col[EMAX];
__device__ int   g_bsum[128];
__device__ int   g_boff[128];
__device__ int   g_is64;
// W1 pre-converted to mma-fragment-major bf16 hi/lo:
// layout [chunk][ hi(512 words) | lo(512 words) ], word idx = (reg*8+nt)*32+lane
__device__ uint32_t g_wf[NCHUNK * 1024];

__device__ __forceinline__ float lrelu(float v) { return v > 0.f ? v : NEG_SLOPE * v; }

__device__ __forceinline__ uint32_t pack_bf16x2(float a, float b) {
    __nv_bfloat162 h = __floats2bfloat162_rn(a, b);
    return *(uint32_t*)&h;
}
__device__ __forceinline__ void split_pair(float a, float b, uint32_t& hi, uint32_t& lo) {
    __nv_bfloat16 ha = __float2bfloat16_rn(a), hb = __float2bfloat16_rn(b);
    float ra = a - __bfloat162float(ha);
    float rb = b - __bfloat162float(hb);
    __nv_bfloat162 hh; hh.x = ha; hh.y = hb;
    hi = *(uint32_t*)&hh;
    lo = pack_bf16x2(ra, rb);
}

__device__ __forceinline__ void mma_bf16(float* c, uint32_t a0, uint32_t a1,
                                         uint32_t a2, uint32_t a3,
                                         uint32_t b0, uint32_t b1) {
    asm("mma.sync.aligned.m16n8k16.row.col.f32.bf16.bf16.f32 "
        "{%0,%1,%2,%3}, {%4,%5,%6,%7}, {%8,%9}, {%0,%1,%2,%3};"
        : "+f"(c[0]), "+f"(c[1]), "+f"(c[2]), "+f"(c[3])
        : "r"(a0), "r"(a1), "r"(a2), "r"(a3), "r"(b0), "r"(b1));
}

// ---------------------------------------------------------------------------
// edge dtype detection
// ---------------------------------------------------------------------------
__global__ void detect_kernel(const long long* p, int N, int E) {
    if (threadIdx.x == 0 && blockIdx.x == 0) {
        int n = E < 64 ? E : 64;
        int ok = 1;
        for (int i = 0; i < n; i++) {
            long long v = p[i];
            if (v < 0 || v >= (long long)N) { ok = 0; break; }
        }
        g_is64 = ok;
    }
}

__global__ void zero_cnt_kernel(int N) {
    int i = blockIdx.x * blockDim.x + threadIdx.x;
    if (i < N) g_cnt[i] = 0;
}

__global__ void count_kernel(const void* ei, int E, int N) {
    int e = blockIdx.x * blockDim.x + threadIdx.x;
    if (e >= E) return;
    int d = g_is64 ? (int)((const long long*)ei)[(size_t)E + e]
                   : ((const int*)ei)[(size_t)E + e];
    atomicAdd(&g_cnt[d], 1);
}

// ---------------------------------------------------------------------------
// multi-block exclusive scan
// ---------------------------------------------------------------------------
__global__ __launch_bounds__(1024) void scan1_kernel(int N) {
    __shared__ int ws[32];
    int tid = threadIdx.x, lane = tid & 31, w = tid >> 5;
    int i = blockIdx.x * 1024 + tid;
    int v = (i < N) ? g_cnt[i] : 0;
    int x = v;
    #pragma unroll
    for (int d = 1; d < 32; d <<= 1) {
        int t = __shfl_up_sync(0xffffffffu, x, d);
        if (lane >= d) x += t;
    }
    if (lane == 31) ws[w] = x;
    __syncthreads();
    if (tid < 32) {
        int s = ws[tid];
        #pragma unroll
        for (int d = 1; d < 32; d <<= 1) {
            int t = __shfl_up_sync(0xffffffffu, s, d);
            if (tid >= d) s += t;
        }
        ws[tid] = s;
    }
    __syncthreads();
    int incl = x + (w > 0 ? ws[w - 1] : 0);
    if (i < N) g_rowptr[i] = incl - v;
    if (tid == 1023) g_bsum[blockIdx.x] = incl;
}

__global__ void scan2_kernel(int NB, int N) {
    __shared__ int ws[4];
    int tid = threadIdx.x, lane = tid & 31, w = tid >> 5;
    int v = (tid < NB) ? g_bsum[tid] : 0;
    int x = v;
    #pragma unroll
    for (int d = 1; d < 32; d <<= 1) {
        int t = __shfl_up_sync(0xffffffffu, x, d);
        if (lane >= d) x += t;
    }
    if (lane == 31) ws[w] = x;
    __syncthreads();
    if (tid < 4) {
        int s = ws[tid];
        for (int d = 1; d < 4; d <<= 1) {
            int t = __shfl_up_sync(0xfu, s, d);
            if (tid >= d) s += t;
        }
        ws[tid] = s;
    }
    __syncthreads();
    int incl = x + (w > 0 ? ws[w - 1] : 0);
    if (tid < NB) g_boff[tid] = incl - v;
    if (tid == NB - 1) g_rowptr[N] = incl;
}

__global__ __launch_bounds__(1024) void scan3_kernel(int N) {
    int i = blockIdx.x * 1024 + threadIdx.x;
    if (i < N) {
        int r = g_rowptr[i] + g_boff[blockIdx.x];
        g_rowptr[i] = r;
        g_head[i] = r;
    }
}

__global__ void scatter_kernel(const void* ei, int E) {
    int e = blockIdx.x * blockDim.x + threadIdx.x;
    if (e >= E) return;
    int s, d;
    if (g_is64) {
        s = (int)((const long long*)ei)[e];
        d = (int)((const long long*)ei)[(size_t)E + e];
    } else {
        s = ((const int*)ei)[e];
        d = ((const int*)ei)[(size_t)E + e];
    }
    int p = atomicAdd(&g_head[d], 1);
    g_col[p] = s;
}

// ---------------------------------------------------------------------------
// W1 -> fragment-major bf16 hi/lo conversion (runs once, 16384 threads)
// frag element for (chunk c, reg r, ntile nt, lane): k = c*16 + r*8 + q*2 (+1),
// n = nt*8 + grp  where grp = lane>>2, q = lane&3.
// ---------------------------------------------------------------------------
__global__ void convW_kernel(const float* __restrict__ W) {
    int t = blockIdx.x * 256 + threadIdx.x;
    if (t >= NCHUNK * 2 * 8 * 32) return;
    int lane = t & 31;
    int nt = (t >> 5) & 7;
    int r  = (t >> 8) & 1;
    int c  = t >> 9;
    int grp = lane >> 2, q = lane & 3;
    int k = c * 16 + r * 8 + q * 2;
    int n = nt * 8 + grp;
    float w0 = W[(size_t)k * HID + n];
    float w1 = W[(size_t)(k + 1) * HID + n];
    uint32_t hi, lo;
    split_pair(w0, w1, hi, lo);
    g_wf[c * 1024 +       (r * 8 + nt) * 32 + lane] = hi;
    g_wf[c * 1024 + 512 + (r * 8 + nt) * 32 + lane] = lo;
}

// ---------------------------------------------------------------------------
// GEMM1: h1[N,64] = x[N,512] @ W1 via mma.sync bf16 hi/lo (3 terms).
// 256 threads = 8 warps x 16 rows. K: 32 chunks of 16, register prefetch.
// ---------------------------------------------------------------------------
#define APAD 10
__global__ __launch_bounds__(256) void gemm1_mma_kernel(const float* __restrict__ x,
                                                        int Nn) {
    __shared__ uint32_t sAh[128 * APAD];
    __shared__ uint32_t sAl[128 * APAD];
    __shared__ uint32_t sW[1024];

    int tid = threadIdx.x;
    int w = tid >> 5, lane = tid & 31;
    int grp = lane >> 2, q = lane & 3;
    int row0 = blockIdx.x * 128;

    // A load assignment: thread covers row = tid>>1, 8 consecutive k at (tid&1)*8
    int arow = tid >> 1;
    int acol8 = (tid & 1) * 8;
    int grow = row0 + arow;
    const float* abase = x + (size_t)(grow < Nn ? grow : (Nn - 1)) * FIN + acol8;

    float acc[8][4];
    #pragma unroll
    for (int nt = 0; nt < 8; nt++)
        #pragma unroll
        for (int i = 0; i < 4; i++) acc[nt][i] = 0.f;

    // prologue prefetch (chunk 0)
    float4 pa0 = *(const float4*)(abase + 0);
    float4 pa1 = *(const float4*)(abase + 4);
    uint4  pw  = *(const uint4*)&g_wf[0 * 1024 + tid * 4];

    for (int c = 0; c < NCHUNK; c++) {
        __syncthreads();   // previous chunk consumed
        // stage A (convert fp32 -> bf16 hi/lo pairs) and W
        {
            uint32_t h0, l0, h1, l1, h2, l2, h3, l3;
            split_pair(pa0.x, pa0.y, h0, l0);
            split_pair(pa0.z, pa0.w, h1, l1);
            split_pair(pa1.x, pa1.y, h2, l2);
            split_pair(pa1.z, pa1.w, h3, l3);
            int off = arow * APAD + (tid & 1) * 4;
            *(uint2*)&sAh[off]     = make_uint2(h0, h1);
            *(uint2*)&sAh[off + 2] = make_uint2(h2, h3);
            *(uint2*)&sAl[off]     = make_uint2(l0, l1);
            *(uint2*)&sAl[off + 2] = make_uint2(l2, l3);
            *(uint4*)&sW[tid * 4] = pw;
        }
        // prefetch next chunk
        if (c + 1 < NCHUNK) {
            pa0 = *(const float4*)(abase + (c + 1) * 16 + 0);
            pa1 = *(const float4*)(abase + (c + 1) * 16 + 4);
            pw  = *(const uint4*)&g_wf[(c + 1) * 1024 + tid * 4];
        }
        __syncthreads();   // smem ready
        // A fragments for this warp's 16 rows
        int ab = w * 16;
        uint32_t ah0 = sAh[(ab + grp) * APAD + q];
        uint32_t ah1 = sAh[(ab + 8 + grp) * APAD + q];
        uint32_t ah2 = sAh[(ab + grp) * APAD + 4 + q];
        uint32_t ah3 = sAh[(ab + 8 + grp) * APAD + 4 + q];
        uint32_t al0 = sAl[(ab + grp) * APAD + q];
        uint32_t al1 = sAl[(ab + 8 + grp) * APAD + q];
        uint32_t al2 = sAl[(ab + grp) * APAD + 4 + q];
        uint32_t al3 = sAl[(ab + 8 + grp) * APAD + 4 + q];
        #pragma unroll
        for (int nt = 0; nt < 8; nt++) {
            uint32_t bh0 = sW[(0 * 8 + nt) * 32 + lane];
            uint32_t bh1 = sW[(1 * 8 + nt) * 32 + lane];
            uint32_t bl0 = sW[512 + (0 * 8 + nt) * 32 + lane];
            uint32_t bl1 = sW[512 + (1 * 8 + nt) * 32 + lane];
            mma_bf16(acc[nt], ah0, ah1, ah2, ah3, bh0, bh1);
            mma_bf16(acc[nt], ah0, ah1, ah2, ah3, bl0, bl1);
            mma_bf16(acc[nt], al0, al1, al2, al3, bh0, bh1);
        }
    }

    // epilogue: c0,c1 -> row ab+grp cols nt*8+2q{,+1}; c2,c3 -> row ab+8+grp
    int r0 = row0 + w * 16 + grp;
    int r1 = r0 + 8;
    #pragma unroll
    for (int nt = 0; nt < 8; nt++) {
        int col = nt * 8 + q * 2;
        if (r0 < Nn) *(float2*)&g_h1[(size_t)r0 * HID + col] = make_float2(acc[nt][0], acc[nt][1]);
        if (r1 < Nn) *(float2*)&g_h1[(size_t)r1 * HID + col] = make_float2(acc[nt][2], acc[nt][3]);
    }
}

// ---------------------------------------------------------------------------
// attention scalars for layer 1
// ---------------------------------------------------------------------------
__global__ __launch_bounds__(256) void attn1_kernel(const float* __restrict__ att_s,
                                                    const float* __restrict__ att_d,
                                                    int N) {
    int node = (blockIdx.x * blockDim.x + threadIdx.x) >> 5;
    int lane = threadIdx.x & 31;
    if (node >= N) return;
    float2 h  = *(const float2*)&g_h1[(size_t)node * HID + 2 * lane];
    float2 as = *(const float2*)&att_s[2 * lane];
    float2 ad = *(const float2*)&att_d[2 * lane];
    float ps = h.x * as.x + h.y * as.y;
    float pd = h.x * ad.x + h.y * ad.y;
    ps += __shfl_xor_sync(0xffffffffu, ps, 1);
    ps += __shfl_xor_sync(0xffffffffu, ps, 2);
    pd += __shfl_xor_sync(0xffffffffu, pd, 1);
    pd += __shfl_xor_sync(0xffffffffu, pd, 2);
    if ((lane & 3) == 0) {
        g_as1[(size_t)node * NH1 + (lane >> 2)] = ps;
        g_ad1[(size_t)node * NH1 + (lane >> 2)] = pd;
    }
}

// ---------------------------------------------------------------------------
// layer-1 segment softmax + aggregation + bias + ELU. One warp per node.
// ---------------------------------------------------------------------------
__global__ __launch_bounds__(256) void agg1_kernel(const float* __restrict__ bias1, int N) {
    int node = (blockIdx.x * blockDim.x + threadIdx.x) >> 5;
    int lane = threadIdx.x & 31;
    if (node >= N) return;
    int start = g_rowptr[node];
    int deg   = g_rowptr[node + 1] - start;

    float ad[8], asl[8];
    {
        float4 u = *(const float4*)&g_ad1[(size_t)node * NH1];
        float4 v = *(const float4*)&g_ad1[(size_t)node * NH1 + 4];
        ad[0]=u.x; ad[1]=u.y; ad[2]=u.z; ad[3]=u.w; ad[4]=v.x; ad[5]=v.y; ad[6]=v.z; ad[7]=v.w;
        float4 a = *(const float4*)&g_as1[(size_t)node * NH1];
        float4 b = *(const float4*)&g_as1[(size_t)node * NH1 + 4];
        asl[0]=a.x; asl[1]=a.y; asl[2]=a.z; asl[3]=a.w; asl[4]=b.x; asl[5]=b.y; asl[6]=b.z; asl[7]=b.w;
    }
    float selfa[8], m[8];
    #pragma unroll
    for (int h = 0; h < 8; h++) { selfa[h] = lrelu(asl[h] + ad[h]); m[h] = selfa[h]; }

    for (int e = lane; e < deg; e += 32) {
        int j = g_col[start + e];
        float4 u = *(const float4*)&g_as1[(size_t)j * NH1];
        float4 v = *(const float4*)&g_as1[(size_t)j * NH1 + 4];
        float aj[8] = {u.x,u.y,u.z,u.w,v.x,v.y,v.z,v.w};
        #pragma unroll
        for (int h = 0; h < 8; h++) m[h] = fmaxf(m[h], lrelu(aj[h] + ad[h]));
    }
    #pragma unroll
    for (int h = 0; h < 8; h++) {
        #pragma unroll
        for (int d = 16; d >= 1; d >>= 1)
            m[h] = fmaxf(m[h], __shfl_xor_sync(0xffffffffu, m[h], d));
    }
    float s[8] = {0,0,0,0,0,0,0,0};
    for (int e = lane; e < deg; e += 32) {
        int j = g_col[start + e];
        float4 u = *(const float4*)&g_as1[(size_t)j * NH1];
        float4 v = *(const float4*)&g_as1[(size_t)j * NH1 + 4];
        float aj[8] = {u.x,u.y,u.z,u.w,v.x,v.y,v.z,v.w};
        #pragma unroll
        for (int h = 0; h < 8; h++) s[h] += __expf(lrelu(aj[h] + ad[h]) - m[h]);
    }
    #pragma unroll
    for (int h = 0; h < 8; h++) {
        #pragma unroll
        for (int d = 16; d >= 1; d >>= 1)
            s[h] += __shfl_xor_sync(0xffffffffu, s[h], d);
        s[h] += __expf(selfa[h] - m[h]);
    }

    int hh = lane >> 2;
    float mh   = m[hh];
    float inv  = 1.f / (s[hh] + EPSV);
    float adh  = ad[hh];
    float wself = __expf(selfa[hh] - mh) * inv;
    float2 hv = *(const float2*)&g_h1[(size_t)node * HID + 2 * lane];
    float ax = wself * hv.x, ay = wself * hv.y;
    for (int e = 0; e < deg; e++) {
        int j = g_col[start + e];
        float a = lrelu(g_as1[(size_t)j * NH1 + hh] + adh);
        float w = __expf(a - mh) * inv;
        float2 v = *(const float2*)&g_h1[(size_t)j * HID + 2 * lane];
        ax = fmaf(w, v.x, ax);
        ay = fmaf(w, v.y, ay);
    }
    float2 bb = *(const float2*)&bias1[2 * lane];
    ax += bb.x; ay += bb.y;
    ax = ax > 0.f ? ax : (__expf(ax) - 1.f);
    ay = ay > 0.f ? ay : (__expf(ay) - 1.f);
    *(float2*)&g_helu[(size_t)node * HID + 2 * lane] = make_float2(ax, ay);
}

// ---------------------------------------------------------------------------
// layer-2 GEMM (thread per node) + attention scalars
// ---------------------------------------------------------------------------
__global__ __launch_bounds__(256) void gemm2_kernel(const float* __restrict__ W2,
                                                    const float* __restrict__ att_s,
                                                    const float* __restrict__ att_d,
                                                    int N) {
    __shared__ float sW[HID * C2];
    __shared__ float sas[C2], sad[C2];
    int tid = threadIdx.x;
    for (int i = tid; i < HID * C2; i += blockDim.x) sW[i] = W2[i];
    if (tid < C2) { sas[tid] = att_s[tid]; sad[tid] = att_d[tid]; }
    __syncthreads();
    int n = blockIdx.x * blockDim.x + tid;
    if (n >= N) return;
    float acc[C2];
    #pragma unroll
    for (int c = 0; c < C2; c++) acc[c] = 0.f;
    const float* hr = &g_helu[(size_t)n * HID];
    #pragma unroll
    for (int k = 0; k < HID; k += 4) {
        float4 h4 = *(const float4*)&hr[k];
        #pragma unroll
        for (int c = 0; c < C2; c++) {
            acc[c] = fmaf(h4.x, sW[(k + 0) * C2 + c], acc[c]);
            acc[c] = fmaf(h4.y, sW[(k + 1) * C2 + c], acc[c]);
            acc[c] = fmaf(h4.z, sW[(k + 2) * C2 + c], acc[c]);
            acc[c] = fmaf(h4.w, sW[(k + 3) * C2 + c], acc[c]);
        }
    }
    #pragma unroll
    for (int c = 0; c < C2; c += 4)
        *(float4*)&g_y2[(size_t)n * C2 + c] = make_float4(acc[c], acc[c+1], acc[c+2], acc[c+3]);
    float ps = 0.f, pd = 0.f;
    #pragma unroll
    for (int c = 0; c < C2; c++) { ps = fmaf(acc[c], sas[c], ps); pd = fmaf(acc[c], sad[c], pd); }
    g_as2[n] = ps;
    g_ad2[n] = pd;
}

// ---------------------------------------------------------------------------
// layer-2 aggregation + bias + final softmax
// ---------------------------------------------------------------------------
__global__ __launch_bounds__(256) void agg2_kernel(const float* __restrict__ bias2,
                                                   float* __restrict__ out, int N) {
    int node = (blockIdx.x * blockDim.x + threadIdx.x) >> 5;
    int lane = threadIdx.x & 31;
    if (node >= N) return;
    int start = g_rowptr[node];
    int deg   = g_rowptr[node + 1] - start;

    float ad    = g_ad2[node];
    float selfa = lrelu(g_as2[node] + ad);
    float m = selfa;
    for (int e = lane; e < deg; e += 32)
        m = fmaxf(m, lrelu(g_as2[g_col[start + e]] + ad));
    #pragma unroll
    for (int d = 16; d >= 1; d >>= 1)
        m = fmaxf(m, __shfl_xor_sync(0xffffffffu, m, d));

    float s = 0.f;
    for (int e = lane; e < deg; e += 32)
        s += __expf(lrelu(g_as2[g_col[start + e]] + ad) - m);
    #pragma unroll
    for (int d = 16; d >= 1; d >>= 1)
        s += __shfl_xor_sync(0xffffffffu, s, d);
    float wself = __expf(selfa - m);
    s += wself;
    float inv = 1.f / (s + EPSV);

    int c = lane & 15, half = lane >> 4;
    float acc = 0.f;
    for (int e = half; e < deg; e += 2) {
        int j = g_col[start + e];
        float w = __expf(lrelu(g_as2[j] + ad) - m) * inv;
        acc = fmaf(w, g_y2[(size_t)j * C2 + c], acc);
    }
    acc += __shfl_xor_sync(0xffffffffu, acc, 16);
    acc = fmaf(wself * inv, g_y2[(size_t)node * C2 + c], acc);
    acc += bias2[c];

    float mx = acc;
    #pragma unroll
    for (int d = 8; d >= 1; d >>= 1)
        mx = fmaxf(mx, __shfl_xor_sync(0xffffffffu, mx, d));
    float p = __expf(acc - mx);
    float ss = p;
    #pragma unroll
    for (int d = 8; d >= 1; d >>= 1)
        ss += __shfl_xor_sync(0xffffffffu, ss, d);
    float soft = p / ss;

    if (lane < 16) {
        out[(size_t)node * C2 + c] = soft;
        out[(size_t)N * C2 + (size_t)node * C2 + c] = acc;
    }
}

// ---------------------------------------------------------------------------
// launch
// ---------------------------------------------------------------------------
extern "C" void kernel_launch(void* const* d_in, const int* in_sizes, int n_in,
                              void* d_out, int out_size) {
    const float* x   = (const float*)d_in[0];
    const void*  ei  = d_in[1];
    const float* W1  = (const float*)d_in[2];
    const float* as1 = (const float*)d_in[3];
    const float* ad1 = (const float*)d_in[4];
    const float* b1  = (const float*)d_in[5];
    const float* W2  = (const float*)d_in[6];
    const float* as2 = (const float*)d_in[7];
    const float* ad2 = (const float*)d_in[8];
    const float* b2  = (const float*)d_in[9];
    float* out = (float*)d_out;

    int E = in_sizes[1] / 2;
    int N = in_sizes[0] / FIN;
    int NB = (N + 1023) / 1024;

    detect_kernel<<<1, 32>>>((const long long*)ei, N, E);
    zero_cnt_kernel<<<(N + 255) / 256, 256>>>(N);
    count_kernel<<<(E + 255) / 256, 256>>>(ei, E, N);
    scan1_kernel<<<NB, 1024>>>(N);
    scan2_kernel<<<1, 128>>>(NB, N);
    scan3_kernel<<<NB, 1024>>>(N);
    scatter_kernel<<<(E + 255) / 256, 256>>>(ei, E);

    convW_kernel<<<64, 256>>>(W1);
    gemm1_mma_kernel<<<(N + 127) / 128, 256>>>(x, N);
    attn1_kernel<<<(N + 7) / 8, 256>>>(as1, ad1, N);
    agg1_kernel<<<(N + 7) / 8, 256>>>(b1, N);
    gemm2_kernel<<<(N + 255) / 256, 256>>>(W2, as2, ad2, N);
    agg2_kernel<<<(N + 7) / 8, 256>>>(b2, out, N);
}

// round 6
// speedup vs baseline: 1.5052x; 1.1273x over previous
#include <cuda_runtime.h>
#include <cuda_bf16.h>
#include <cstdint>

// ---------------------------------------------------------------------------
// Problem constants
// ---------------------------------------------------------------------------
#define NMAX 100000
#define EMAX 1600000
#define FIN  512
#define HID  64
#define NH1  8
#define C2   16
#define NEG_SLOPE 0.2f
#define EPSV 1e-16f
#define NCHUNK 32            // K chunks of 16

// ---------------------------------------------------------------------------
// Device scratch
// ---------------------------------------------------------------------------
__device__ float g_h1[(size_t)NMAX * HID];
__device__ float g_helu[(size_t)NMAX * HID];
__device__ float g_y2[(size_t)NMAX * C2];
__device__ float g_as1[(size_t)NMAX * NH1];
__device__ float g_ad1[(size_t)NMAX * NH1];
__device__ float g_as2[NMAX];
__device__ float g_ad2[NMAX];
__device__ int   g_rowptr[NMAX + 1];
__device__ int   g_head[NMAX];
__device__ int   g_cnt[NMAX];
__device__ int   g_col[EMAX];
__device__ int   g_bsum[128];
__device__ int   g_boff[128];
__device__ int   g_is64;
// W1 pre-converted to mma-fragment-major bf16 hi/lo:
// layout [chunk][ hi(512 words) | lo(512 words) ], word idx = (reg*8+nt)*32+lane
__device__ uint32_t g_wf[NCHUNK * 1024];

__device__ __forceinline__ float lrelu(float v) { return v > 0.f ? v : NEG_SLOPE * v; }

__device__ __forceinline__ uint32_t pack_bf16x2(float a, float b) {
    __nv_bfloat162 h = __floats2bfloat162_rn(a, b);
    return *(uint32_t*)&h;
}
__device__ __forceinline__ void split_pair(float a, float b, uint32_t& hi, uint32_t& lo) {
    __nv_bfloat16 ha = __float2bfloat16_rn(a), hb = __float2bfloat16_rn(b);
    float ra = a - __bfloat162float(ha);
    float rb = b - __bfloat162float(hb);
    __nv_bfloat162 hh; hh.x = ha; hh.y = hb;
    hi = *(uint32_t*)&hh;
    lo = pack_bf16x2(ra, rb);
}

__device__ __forceinline__ void mma_bf16(float* c, uint32_t a0, uint32_t a1,
                                         uint32_t a2, uint32_t a3,
                                         uint32_t b0, uint32_t b1) {
    asm("mma.sync.aligned.m16n8k16.row.col.f32.bf16.bf16.f32 "
        "{%0,%1,%2,%3}, {%4,%5,%6,%7}, {%8,%9}, {%0,%1,%2,%3};"
        : "+f"(c[0]), "+f"(c[1]), "+f"(c[2]), "+f"(c[3])
        : "r"(a0), "r"(a1), "r"(a2), "r"(a3), "r"(b0), "r"(b1));
}

// ---------------------------------------------------------------------------
// edge dtype detection
// ---------------------------------------------------------------------------
__global__ void detect_kernel(const long long* p, int N, int E) {
    if (threadIdx.x == 0 && blockIdx.x == 0) {
        int n = E < 64 ? E : 64;
        int ok = 1;
        for (int i = 0; i < n; i++) {
            long long v = p[i];
            if (v < 0 || v >= (long long)N) { ok = 0; break; }
        }
        g_is64 = ok;
    }
}

__global__ void zero_cnt_kernel(int N) {
    int i = blockIdx.x * blockDim.x + threadIdx.x;
    if (i < N) g_cnt[i] = 0;
}

__global__ void count_kernel(const void* ei, int E, int N) {
    int e = blockIdx.x * blockDim.x + threadIdx.x;
    if (e >= E) return;
    int d = g_is64 ? (int)((const long long*)ei)[(size_t)E + e]
                   : ((const int*)ei)[(size_t)E + e];
    atomicAdd(&g_cnt[d], 1);
}

// ---------------------------------------------------------------------------
// multi-block exclusive scan
// ---------------------------------------------------------------------------
__global__ __launch_bounds__(1024) void scan1_kernel(int N) {
    __shared__ int ws[32];
    int tid = threadIdx.x, lane = tid & 31, w = tid >> 5;
    int i = blockIdx.x * 1024 + tid;
    int v = (i < N) ? g_cnt[i] : 0;
    int x = v;
    #pragma unroll
    for (int d = 1; d < 32; d <<= 1) {
        int t = __shfl_up_sync(0xffffffffu, x, d);
        if (lane >= d) x += t;
    }
    if (lane == 31) ws[w] = x;
    __syncthreads();
    if (tid < 32) {
        int s = ws[tid];
        #pragma unroll
        for (int d = 1; d < 32; d <<= 1) {
            int t = __shfl_up_sync(0xffffffffu, s, d);
            if (tid >= d) s += t;
        }
        ws[tid] = s;
    }
    __syncthreads();
    int incl = x + (w > 0 ? ws[w - 1] : 0);
    if (i < N) g_rowptr[i] = incl - v;
    if (tid == 1023) g_bsum[blockIdx.x] = incl;
}

__global__ void scan2_kernel(int NB, int N) {
    __shared__ int ws[4];
    int tid = threadIdx.x, lane = tid & 31, w = tid >> 5;
    int v = (tid < NB) ? g_bsum[tid] : 0;
    int x = v;
    #pragma unroll
    for (int d = 1; d < 32; d <<= 1) {
        int t = __shfl_up_sync(0xffffffffu, x, d);
        if (lane >= d) x += t;
    }
    if (lane == 31) ws[w] = x;
    __syncthreads();
    if (tid < 4) {
        int s = ws[tid];
        for (int d = 1; d < 4; d <<= 1) {
            int t = __shfl_up_sync(0xfu, s, d);
            if (tid >= d) s += t;
        }
        ws[tid] = s;
    }
    __syncthreads();
    int incl = x + (w > 0 ? ws[w - 1] : 0);
    if (tid < NB) g_boff[tid] = incl - v;
    if (tid == NB - 1) g_rowptr[N] = incl;
}

__global__ __launch_bounds__(1024) void scan3_kernel(int N) {
    int i = blockIdx.x * 1024 + threadIdx.x;
    if (i < N) {
        int r = g_rowptr[i] + g_boff[blockIdx.x];
        g_rowptr[i] = r;
        g_head[i] = r;
    }
}

__global__ void scatter_kernel(const void* ei, int E) {
    int e = blockIdx.x * blockDim.x + threadIdx.x;
    if (e >= E) return;
    int s, d;
    if (g_is64) {
        s = (int)((const long long*)ei)[e];
        d = (int)((const long long*)ei)[(size_t)E + e];
    } else {
        s = ((const int*)ei)[e];
        d = ((const int*)ei)[(size_t)E + e];
    }
    int p = atomicAdd(&g_head[d], 1);
    g_col[p] = s;
}

// ---------------------------------------------------------------------------
// W1 -> fragment-major bf16 hi/lo conversion (runs once, 16384 threads)
// ---------------------------------------------------------------------------
__global__ void convW_kernel(const float* __restrict__ W) {
    int t = blockIdx.x * 256 + threadIdx.x;
    if (t >= NCHUNK * 2 * 8 * 32) return;
    int lane = t & 31;
    int nt = (t >> 5) & 7;
    int r  = (t >> 8) & 1;
    int c  = t >> 9;
    int grp = lane >> 2, q = lane & 3;
    int k = c * 16 + r * 8 + q * 2;
    int n = nt * 8 + grp;
    float w0 = W[(size_t)k * HID + n];
    float w1 = W[(size_t)(k + 1) * HID + n];
    uint32_t hi, lo;
    split_pair(w0, w1, hi, lo);
    g_wf[c * 1024 +       (r * 8 + nt) * 32 + lane] = hi;
    g_wf[c * 1024 + 512 + (r * 8 + nt) * 32 + lane] = lo;
}

// ---------------------------------------------------------------------------
// GEMM1: h1[N,64] = x[N,512] @ W1 via mma.sync bf16 hi/lo (3 terms).
// 256 threads = 8 warps x 16 rows. Fused attn1 epilogue (head == n-tile).
// ---------------------------------------------------------------------------
#define APAD 10
__global__ __launch_bounds__(256) void gemm1_mma_kernel(const float* __restrict__ x,
                                                        const float* __restrict__ att_s,
                                                        const float* __restrict__ att_d,
                                                        int Nn) {
    __shared__ uint32_t sAh[128 * APAD];
    __shared__ uint32_t sAl[128 * APAD];
    __shared__ uint32_t sW[1024];

    int tid = threadIdx.x;
    int w = tid >> 5, lane = tid & 31;
    int grp = lane >> 2, q = lane & 3;
    int row0 = blockIdx.x * 128;

    int arow = tid >> 1;
    int acol8 = (tid & 1) * 8;
    int grow_a = row0 + arow;
    const float* abase = x + (size_t)(grow_a < Nn ? grow_a : (Nn - 1)) * FIN + acol8;

    float acc[8][4];
    #pragma unroll
    for (int nt = 0; nt < 8; nt++)
        #pragma unroll
        for (int i = 0; i < 4; i++) acc[nt][i] = 0.f;

    float4 pa0 = *(const float4*)(abase + 0);
    float4 pa1 = *(const float4*)(abase + 4);
    uint4  pw  = *(const uint4*)&g_wf[0 * 1024 + tid * 4];

    for (int c = 0; c < NCHUNK; c++) {
        __syncthreads();
        {
            uint32_t h0, l0, h1, l1, h2, l2, h3, l3;
            split_pair(pa0.x, pa0.y, h0, l0);
            split_pair(pa0.z, pa0.w, h1, l1);
            split_pair(pa1.x, pa1.y, h2, l2);
            split_pair(pa1.z, pa1.w, h3, l3);
            int off = arow * APAD + (tid & 1) * 4;
            *(uint2*)&sAh[off]     = make_uint2(h0, h1);
            *(uint2*)&sAh[off + 2] = make_uint2(h2, h3);
            *(uint2*)&sAl[off]     = make_uint2(l0, l1);
            *(uint2*)&sAl[off + 2] = make_uint2(l2, l3);
            *(uint4*)&sW[tid * 4] = pw;
        }
        if (c + 1 < NCHUNK) {
            pa0 = *(const float4*)(abase + (c + 1) * 16 + 0);
            pa1 = *(const float4*)(abase + (c + 1) * 16 + 4);
            pw  = *(const uint4*)&g_wf[(c + 1) * 1024 + tid * 4];
        }
        __syncthreads();
        int ab = w * 16;
        uint32_t ah0 = sAh[(ab + grp) * APAD + q];
        uint32_t ah1 = sAh[(ab + 8 + grp) * APAD + q];
        uint32_t ah2 = sAh[(ab + grp) * APAD + 4 + q];
        uint32_t ah3 = sAh[(ab + 8 + grp) * APAD + 4 + q];
        uint32_t al0 = sAl[(ab + grp) * APAD + q];
        uint32_t al1 = sAl[(ab + 8 + grp) * APAD + q];
        uint32_t al2 = sAl[(ab + grp) * APAD + 4 + q];
        uint32_t al3 = sAl[(ab + 8 + grp) * APAD + 4 + q];
        #pragma unroll
        for (int nt = 0; nt < 8; nt++) {
            uint32_t bh0 = sW[(0 * 8 + nt) * 32 + lane];
            uint32_t bh1 = sW[(1 * 8 + nt) * 32 + lane];
            uint32_t bl0 = sW[512 + (0 * 8 + nt) * 32 + lane];
            uint32_t bl1 = sW[512 + (1 * 8 + nt) * 32 + lane];
            mma_bf16(acc[nt], ah0, ah1, ah2, ah3, bh0, bh1);
            mma_bf16(acc[nt], ah0, ah1, ah2, ah3, bl0, bl1);
            mma_bf16(acc[nt], al0, al1, al2, al3, bh0, bh1);
        }
    }

    // epilogue: store h1 + fused per-head attention dots (head == nt)
    int r0 = row0 + w * 16 + grp;
    int r1 = r0 + 8;
    #pragma unroll
    for (int nt = 0; nt < 8; nt++) {
        int col = nt * 8 + q * 2;
        if (r0 < Nn) *(float2*)&g_h1[(size_t)r0 * HID + col] = make_float2(acc[nt][0], acc[nt][1]);
        if (r1 < Nn) *(float2*)&g_h1[(size_t)r1 * HID + col] = make_float2(acc[nt][2], acc[nt][3]);
        float2 a_s = *(const float2*)&att_s[col];
        float2 a_d = *(const float2*)&att_d[col];
        float p0s = acc[nt][0] * a_s.x + acc[nt][1] * a_s.y;
        float p0d = acc[nt][0] * a_d.x + acc[nt][1] * a_d.y;
        float p1s = acc[nt][2] * a_s.x + acc[nt][3] * a_s.y;
        float p1d = acc[nt][2] * a_d.x + acc[nt][3] * a_d.y;
        p0s += __shfl_xor_sync(0xffffffffu, p0s, 1);
        p0s += __shfl_xor_sync(0xffffffffu, p0s, 2);
        p0d += __shfl_xor_sync(0xffffffffu, p0d, 1);
        p0d += __shfl_xor_sync(0xffffffffu, p0d, 2);
        p1s += __shfl_xor_sync(0xffffffffu, p1s, 1);
        p1s += __shfl_xor_sync(0xffffffffu, p1s, 2);
        p1d += __shfl_xor_sync(0xffffffffu, p1d, 1);
        p1d += __shfl_xor_sync(0xffffffffu, p1d, 2);
        if (q == 0) {
            if (r0 < Nn) { g_as1[(size_t)r0 * NH1 + nt] = p0s; g_ad1[(size_t)r0 * NH1 + nt] = p0d; }
            if (r1 < Nn) { g_as1[(size_t)r1 * NH1 + nt] = p1s; g_ad1[(size_t)r1 * NH1 + nt] = p1d; }
        }
    }
}

// ---------------------------------------------------------------------------
// layer-1 fused softmax+aggregate, SINGLE PASS (no max subtraction; logits
// bounded by construction). One warp per node. Lanes = (4 edges x 8 heads)
// for weight computation; lane owns feature comps 2l,2l+1 for accumulation.
// ---------------------------------------------------------------------------
__global__ __launch_bounds__(256) void agg1_kernel(const float* __restrict__ bias1, int N) {
    int node = (blockIdx.x * blockDim.x + threadIdx.x) >> 5;
    int lane = threadIdx.x & 31;
    if (node >= N) return;
    int start = g_rowptr[node];
    int deg   = g_rowptr[node + 1] - start;
    int hl = lane & 7;        // head owned for weight computation
    int hh = lane >> 2;       // head of owned feature comps

    float adv   = g_ad1[(size_t)node * NH1 + hl];
    float selfe = __expf(lrelu(g_as1[(size_t)node * NH1 + hl] + adv));
    float2 hv = *(const float2*)&g_h1[(size_t)node * HID + 2 * lane];

    float ax = 0.f, ay = 0.f;
    float s = 0.f;
    for (int base = 0; base < deg; base += 4) {
        int idx = base + (lane >> 3);
        int j = 0; float wt = 0.f;
        if (idx < deg) {
            j = g_col[start + idx];
            wt = __expf(lrelu(g_as1[(size_t)j * NH1 + hl] + adv));
        }
        s += wt;
        int nb = min(4, deg - base);
        #pragma unroll
        for (int e = 0; e < 4; e++) {
            if (e >= nb) break;                       // nb warp-uniform
            float we = __shfl_sync(0xffffffffu, wt, e * 8 + hh);
            int je   = __shfl_sync(0xffffffffu, j, e * 8);
            float2 v = *(const float2*)&g_h1[(size_t)je * HID + 2 * lane];
            ax = fmaf(we, v.x, ax);
            ay = fmaf(we, v.y, ay);
        }
    }
    // reduce s over the 4 edge-groups (lane bits 3,4)
    s += __shfl_xor_sync(0xffffffffu, s, 8);
    s += __shfl_xor_sync(0xffffffffu, s, 16);
    s += selfe;
    float inv = 1.f / (s + EPSV);
    float invB   = __shfl_sync(0xffffffffu, inv, hh);    // lanes 0-7 hold heads 0-7
    float selfeB = __shfl_sync(0xffffffffu, selfe, hh);
    ax = (ax + selfeB * hv.x) * invB;
    ay = (ay + selfeB * hv.y) * invB;
    float2 bb = *(const float2*)&bias1[2 * lane];
    ax += bb.x; ay += bb.y;
    ax = ax > 0.f ? ax : (__expf(ax) - 1.f);
    ay = ay > 0.f ? ay : (__expf(ay) - 1.f);
    *(float2*)&g_helu[(size_t)node * HID + 2 * lane] = make_float2(ax, ay);
}

// ---------------------------------------------------------------------------
// layer-2 GEMM (thread per node) + attention scalars
// ---------------------------------------------------------------------------
__global__ __launch_bounds__(256) void gemm2_kernel(const float* __restrict__ W2,
                                                    const float* __restrict__ att_s,
                                                    const float* __restrict__ att_d,
                                                    int N) {
    __shared__ float sW[HID * C2];
    __shared__ float sas[C2], sad[C2];
    int tid = threadIdx.x;
    for (int i = tid; i < HID * C2; i += blockDim.x) sW[i] = W2[i];
    if (tid < C2) { sas[tid] = att_s[tid]; sad[tid] = att_d[tid]; }
    __syncthreads();
    int n = blockIdx.x * blockDim.x + tid;
    if (n >= N) return;
    float acc[C2];
    #pragma unroll
    for (int c = 0; c < C2; c++) acc[c] = 0.f;
    const float* hr = &g_helu[(size_t)n * HID];
    #pragma unroll
    for (int k = 0; k < HID; k += 4) {
        float4 h4 = *(const float4*)&hr[k];
        #pragma unroll
        for (int c = 0; c < C2; c++) {
            acc[c] = fmaf(h4.x, sW[(k + 0) * C2 + c], acc[c]);
            acc[c] = fmaf(h4.y, sW[(k + 1) * C2 + c], acc[c]);
            acc[c] = fmaf(h4.z, sW[(k + 2) * C2 + c], acc[c]);
            acc[c] = fmaf(h4.w, sW[(k + 3) * C2 + c], acc[c]);
        }
    }
    #pragma unroll
    for (int c = 0; c < C2; c += 4)
        *(float4*)&g_y2[(size_t)n * C2 + c] = make_float4(acc[c], acc[c+1], acc[c+2], acc[c+3]);
    float ps = 0.f, pd = 0.f;
    #pragma unroll
    for (int c = 0; c < C2; c++) { ps = fmaf(acc[c], sas[c], ps); pd = fmaf(acc[c], sad[c], pd); }
    g_as2[n] = ps;
    g_ad2[n] = pd;
}

// ---------------------------------------------------------------------------
// layer-2 fused softmax+aggregate, SINGLE PASS + bias + final softmax
// ---------------------------------------------------------------------------
__global__ __launch_bounds__(256) void agg2_kernel(const float* __restrict__ bias2,
                                                   float* __restrict__ out, int N) {
    int node = (blockIdx.x * blockDim.x + threadIdx.x) >> 5;
    int lane = threadIdx.x & 31;
    if (node >= N) return;
    int start = g_rowptr[node];
    int deg   = g_rowptr[node + 1] - start;

    float ad    = g_ad2[node];
    float selfe = __expf(lrelu(g_as2[node] + ad));
    int c = lane & 15, half = lane >> 4;

    float acc = 0.f;
    float s = 0.f;
    for (int base = 0; base < deg; base += 32) {
        int idx = base + lane;
        int j = 0; float wt = 0.f;
        if (idx < deg) {
            j = g_col[start + idx];
            wt = __expf(lrelu(g_as2[j] + ad));
        }
        s += wt;
        int nb = min(32, deg - base);
        for (int p = 0; p < nb; p += 2) {           // trip count warp-uniform
            int e = p + half;
            float we = __shfl_sync(0xffffffffu, wt, e & 31);
            int je   = __shfl_sync(0xffffffffu, j, e & 31);
            if (e < nb) acc = fmaf(we, g_y2[(size_t)je * C2 + c], acc);
        }
    }
    #pragma unroll
    for (int d = 16; d >= 1; d >>= 1)
        s += __shfl_xor_sync(0xffffffffu, s, d);
    s += selfe;
    float inv = 1.f / (s + EPSV);

    acc += __shfl_xor_sync(0xffffffffu, acc, 16);   // combine halves
    acc = (acc + selfe * g_y2[(size_t)node * C2 + c]) * inv;
    acc += bias2[c];

    // softmax over the 16 components (halves carry identical values)
    float mx = acc;
    #pragma unroll
    for (int d = 8; d >= 1; d >>= 1)
        mx = fmaxf(mx, __shfl_xor_sync(0xffffffffu, mx, d));
    float p = __expf(acc - mx);
    float ss = p;
    #pragma unroll
    for (int d = 8; d >= 1; d >>= 1)
        ss += __shfl_xor_sync(0xffffffffu, ss, d);
    float soft = p / ss;

    if (lane < 16) {
        out[(size_t)node * C2 + c] = soft;
        out[(size_t)N * C2 + (size_t)node * C2 + c] = acc;
    }
}

// ---------------------------------------------------------------------------
// launch
// ---------------------------------------------------------------------------
extern "C" void kernel_launch(void* const* d_in, const int* in_sizes, int n_in,
                              void* d_out, int out_size) {
    const float* x   = (const float*)d_in[0];
    const void*  ei  = d_in[1];
    const float* W1  = (const float*)d_in[2];
    const float* as1 = (const float*)d_in[3];
    const float* ad1 = (const float*)d_in[4];
    const float* b1  = (const float*)d_in[5];
    const float* W2  = (const float*)d_in[6];
    const float* as2 = (const float*)d_in[7];
    const float* ad2 = (const float*)d_in[8];
    const float* b2  = (const float*)d_in[9];
    float* out = (float*)d_out;

    int E = in_sizes[1] / 2;
    int N = in_sizes[0] / FIN;
    int NB = (N + 1023) / 1024;

    detect_kernel<<<1, 32>>>((const long long*)ei, N, E);
    zero_cnt_kernel<<<(N + 255) / 256, 256>>>(N);
    count_kernel<<<(E + 255) / 256, 256>>>(ei, E, N);
    scan1_kernel<<<NB, 1024>>>(N);
    scan2_kernel<<<1, 128>>>(NB, N);
    scan3_kernel<<<NB, 1024>>>(N);
    scatter_kernel<<<(E + 255) / 256, 256>>>(ei, E);

    convW_kernel<<<64, 256>>>(W1);
    gemm1_mma_kernel<<<(N + 127) / 128, 256>>>(x, as1, ad1, N);
    agg1_kernel<<<(N + 7) / 8, 256>>>(b1, N);
    gemm2_kernel<<<(N + 255) / 256, 256>>>(W2, as2, ad2, N);
    agg2_kernel<<<(N + 7) / 8, 256>>>(b2, out, N);
}

// round 7
// speedup vs baseline: 1.6599x; 1.1028x over previous
#include <cuda_runtime.h>
#include <cuda_bf16.h>
#include <cstdint>

// ---------------------------------------------------------------------------
// Problem constants
// ---------------------------------------------------------------------------
#define NMAX 100000
#define EMAX 1600000
#define FIN  512
#define HID  64
#define NH1  8
#define C2   16
#define NEG_SLOPE 0.2f
#define EPSV 1e-16f
#define NCHUNK 32            // K chunks of 16

// ---------------------------------------------------------------------------
// Device scratch
// ---------------------------------------------------------------------------
__device__ float g_h1[(size_t)NMAX * HID];
__device__ float g_helu[(size_t)NMAX * HID];
__device__ float g_y2[(size_t)NMAX * C2];
__device__ float g_as1[(size_t)NMAX * NH1];
__device__ float g_ad1[(size_t)NMAX * NH1];
__device__ float g_as2[NMAX];
__device__ float g_ad2[NMAX];
__device__ int   g_rowptr[NMAX + 1];
__device__ int   g_head[NMAX];
__device__ int   g_cnt[NMAX];
__device__ int   g_col[EMAX];
__device__ int   g_bsum[128];
__device__ int   g_boff[128];
__device__ int   g_is64;
// W1 pre-converted to mma-fragment-major bf16 hi/lo
__device__ uint32_t g_wf[NCHUNK * 1024];

__device__ __forceinline__ float lrelu(float v) { return v > 0.f ? v : NEG_SLOPE * v; }

__device__ __forceinline__ uint32_t pack_bf16x2(float a, float b) {
    __nv_bfloat162 h = __floats2bfloat162_rn(a, b);
    return *(uint32_t*)&h;
}
__device__ __forceinline__ void split_pair(float a, float b, uint32_t& hi, uint32_t& lo) {
    __nv_bfloat16 ha = __float2bfloat16_rn(a), hb = __float2bfloat16_rn(b);
    float ra = a - __bfloat162float(ha);
    float rb = b - __bfloat162float(hb);
    __nv_bfloat162 hh; hh.x = ha; hh.y = hb;
    hi = *(uint32_t*)&hh;
    lo = pack_bf16x2(ra, rb);
}

__device__ __forceinline__ void mma_bf16(float* c, uint32_t a0, uint32_t a1,
                                         uint32_t a2, uint32_t a3,
                                         uint32_t b0, uint32_t b1) {
    asm("mma.sync.aligned.m16n8k16.row.col.f32.bf16.bf16.f32 "
        "{%0,%1,%2,%3}, {%4,%5,%6,%7}, {%8,%9}, {%0,%1,%2,%3};"
        : "+f"(c[0]), "+f"(c[1]), "+f"(c[2]), "+f"(c[3])
        : "r"(a0), "r"(a1), "r"(a2), "r"(a3), "r"(b0), "r"(b1));
}

// ---------------------------------------------------------------------------
// edge dtype detection
// ---------------------------------------------------------------------------
__global__ void detect_kernel(const long long* p, int N, int E) {
    if (threadIdx.x == 0 && blockIdx.x == 0) {
        int n = E < 64 ? E : 64;
        int ok = 1;
        for (int i = 0; i < n; i++) {
            long long v = p[i];
            if (v < 0 || v >= (long long)N) { ok = 0; break; }
        }
        g_is64 = ok;
    }
}

__global__ void zero_cnt_kernel(int N) {
    int i = blockIdx.x * blockDim.x + threadIdx.x;
    if (i < N) g_cnt[i] = 0;
}

__global__ void count_kernel(const void* ei, int E, int N) {
    int e = blockIdx.x * blockDim.x + threadIdx.x;
    if (e >= E) return;
    int d = g_is64 ? (int)((const long long*)ei)[(size_t)E + e]
                   : ((const int*)ei)[(size_t)E + e];
    atomicAdd(&g_cnt[d], 1);
}

// ---------------------------------------------------------------------------
// multi-block exclusive scan
// ---------------------------------------------------------------------------
__global__ __launch_bounds__(1024) void scan1_kernel(int N) {
    __shared__ int ws[32];
    int tid = threadIdx.x, lane = tid & 31, w = tid >> 5;
    int i = blockIdx.x * 1024 + tid;
    int v = (i < N) ? g_cnt[i] : 0;
    int x = v;
    #pragma unroll
    for (int d = 1; d < 32; d <<= 1) {
        int t = __shfl_up_sync(0xffffffffu, x, d);
        if (lane >= d) x += t;
    }
    if (lane == 31) ws[w] = x;
    __syncthreads();
    if (tid < 32) {
        int s = ws[tid];
        #pragma unroll
        for (int d = 1; d < 32; d <<= 1) {
            int t = __shfl_up_sync(0xffffffffu, s, d);
            if (tid >= d) s += t;
        }
        ws[tid] = s;
    }
    __syncthreads();
    int incl = x + (w > 0 ? ws[w - 1] : 0);
    if (i < N) g_rowptr[i] = incl - v;
    if (tid == 1023) g_bsum[blockIdx.x] = incl;
}

__global__ void scan2_kernel(int NB, int N) {
    __shared__ int ws[4];
    int tid = threadIdx.x, lane = tid & 31, w = tid >> 5;
    int v = (tid < NB) ? g_bsum[tid] : 0;
    int x = v;
    #pragma unroll
    for (int d = 1; d < 32; d <<= 1) {
        int t = __shfl_up_sync(0xffffffffu, x, d);
        if (lane >= d) x += t;
    }
    if (lane == 31) ws[w] = x;
    __syncthreads();
    if (tid < 4) {
        int s = ws[tid];
        for (int d = 1; d < 4; d <<= 1) {
            int t = __shfl_up_sync(0xfu, s, d);
            if (tid >= d) s += t;
        }
        ws[tid] = s;
    }
    __syncthreads();
    int incl = x + (w > 0 ? ws[w - 1] : 0);
    if (tid < NB) g_boff[tid] = incl - v;
    if (tid == NB - 1) g_rowptr[N] = incl;
}

__global__ __launch_bounds__(1024) void scan3_kernel(int N) {
    int i = blockIdx.x * 1024 + threadIdx.x;
    if (i < N) {
        int r = g_rowptr[i] + g_boff[blockIdx.x];
        g_rowptr[i] = r;
        g_head[i] = r;
    }
}

__global__ void scatter_kernel(const void* ei, int E) {
    int e = blockIdx.x * blockDim.x + threadIdx.x;
    if (e >= E) return;
    int s, d;
    if (g_is64) {
        s = (int)((const long long*)ei)[e];
        d = (int)((const long long*)ei)[(size_t)E + e];
    } else {
        s = ((const int*)ei)[e];
        d = ((const int*)ei)[(size_t)E + e];
    }
    int p = atomicAdd(&g_head[d], 1);
    g_col[p] = s;
}

// ---------------------------------------------------------------------------
// W1 -> fragment-major bf16 hi/lo conversion (runs once, 16384 threads)
// ---------------------------------------------------------------------------
__global__ void convW_kernel(const float* __restrict__ W) {
    int t = blockIdx.x * 256 + threadIdx.x;
    if (t >= NCHUNK * 2 * 8 * 32) return;
    int lane = t & 31;
    int nt = (t >> 5) & 7;
    int r  = (t >> 8) & 1;
    int c  = t >> 9;
    int grp = lane >> 2, q = lane & 3;
    int k = c * 16 + r * 8 + q * 2;
    int n = nt * 8 + grp;
    float w0 = W[(size_t)k * HID + n];
    float w1 = W[(size_t)(k + 1) * HID + n];
    uint32_t hi, lo;
    split_pair(w0, w1, hi, lo);
    g_wf[c * 1024 +       (r * 8 + nt) * 32 + lane] = hi;
    g_wf[c * 1024 + 512 + (r * 8 + nt) * 32 + lane] = lo;
}

// ---------------------------------------------------------------------------
// GEMM1: h1[N,64] = x[N,512] @ W1 via mma.sync bf16 hi/lo (3 terms).
// 256 threads = 8 warps x 16 rows. Fused attn1 epilogue (head == n-tile).
// ---------------------------------------------------------------------------
#define APAD 10
__global__ __launch_bounds__(256) void gemm1_mma_kernel(const float* __restrict__ x,
                                                        const float* __restrict__ att_s,
                                                        const float* __restrict__ att_d,
                                                        int Nn) {
    __shared__ uint32_t sAh[128 * APAD];
    __shared__ uint32_t sAl[128 * APAD];
    __shared__ uint32_t sW[1024];

    int tid = threadIdx.x;
    int w = tid >> 5, lane = tid & 31;
    int grp = lane >> 2, q = lane & 3;
    int row0 = blockIdx.x * 128;

    int arow = tid >> 1;
    int acol8 = (tid & 1) * 8;
    int grow_a = row0 + arow;
    const float* abase = x + (size_t)(grow_a < Nn ? grow_a : (Nn - 1)) * FIN + acol8;

    float acc[8][4];
    #pragma unroll
    for (int nt = 0; nt < 8; nt++)
        #pragma unroll
        for (int i = 0; i < 4; i++) acc[nt][i] = 0.f;

    float4 pa0 = *(const float4*)(abase + 0);
    float4 pa1 = *(const float4*)(abase + 4);
    uint4  pw  = *(const uint4*)&g_wf[0 * 1024 + tid * 4];

    for (int c = 0; c < NCHUNK; c++) {
        __syncthreads();
        {
            uint32_t h0, l0, h1, l1, h2, l2, h3, l3;
            split_pair(pa0.x, pa0.y, h0, l0);
            split_pair(pa0.z, pa0.w, h1, l1);
            split_pair(pa1.x, pa1.y, h2, l2);
            split_pair(pa1.z, pa1.w, h3, l3);
            int off = arow * APAD + (tid & 1) * 4;
            *(uint2*)&sAh[off]     = make_uint2(h0, h1);
            *(uint2*)&sAh[off + 2] = make_uint2(h2, h3);
            *(uint2*)&sAl[off]     = make_uint2(l0, l1);
            *(uint2*)&sAl[off + 2] = make_uint2(l2, l3);
            *(uint4*)&sW[tid * 4] = pw;
        }
        if (c + 1 < NCHUNK) {
            pa0 = *(const float4*)(abase + (c + 1) * 16 + 0);
            pa1 = *(const float4*)(abase + (c + 1) * 16 + 4);
            pw  = *(const uint4*)&g_wf[(c + 1) * 1024 + tid * 4];
        }
        __syncthreads();
        int ab = w * 16;
        uint32_t ah0 = sAh[(ab + grp) * APAD + q];
        uint32_t ah1 = sAh[(ab + 8 + grp) * APAD + q];
        uint32_t ah2 = sAh[(ab + grp) * APAD + 4 + q];
        uint32_t ah3 = sAh[(ab + 8 + grp) * APAD + 4 + q];
        uint32_t al0 = sAl[(ab + grp) * APAD + q];
        uint32_t al1 = sAl[(ab + 8 + grp) * APAD + q];
        uint32_t al2 = sAl[(ab + grp) * APAD + 4 + q];
        uint32_t al3 = sAl[(ab + 8 + grp) * APAD + 4 + q];
        #pragma unroll
        for (int nt = 0; nt < 8; nt++) {
            uint32_t bh0 = sW[(0 * 8 + nt) * 32 + lane];
            uint32_t bh1 = sW[(1 * 8 + nt) * 32 + lane];
            uint32_t bl0 = sW[512 + (0 * 8 + nt) * 32 + lane];
            uint32_t bl1 = sW[512 + (1 * 8 + nt) * 32 + lane];
            mma_bf16(acc[nt], ah0, ah1, ah2, ah3, bh0, bh1);
            mma_bf16(acc[nt], ah0, ah1, ah2, ah3, bl0, bl1);
            mma_bf16(acc[nt], al0, al1, al2, al3, bh0, bh1);
        }
    }

    // epilogue: store h1 + fused per-head attention dots (head == nt)
    int r0 = row0 + w * 16 + grp;
    int r1 = r0 + 8;
    #pragma unroll
    for (int nt = 0; nt < 8; nt++) {
        int col = nt * 8 + q * 2;
        if (r0 < Nn) *(float2*)&g_h1[(size_t)r0 * HID + col] = make_float2(acc[nt][0], acc[nt][1]);
        if (r1 < Nn) *(float2*)&g_h1[(size_t)r1 * HID + col] = make_float2(acc[nt][2], acc[nt][3]);
        float2 a_s = *(const float2*)&att_s[col];
        float2 a_d = *(const float2*)&att_d[col];
        float p0s = acc[nt][0] * a_s.x + acc[nt][1] * a_s.y;
        float p0d = acc[nt][0] * a_d.x + acc[nt][1] * a_d.y;
        float p1s = acc[nt][2] * a_s.x + acc[nt][3] * a_s.y;
        float p1d = acc[nt][2] * a_d.x + acc[nt][3] * a_d.y;
        p0s += __shfl_xor_sync(0xffffffffu, p0s, 1);
        p0s += __shfl_xor_sync(0xffffffffu, p0s, 2);
        p0d += __shfl_xor_sync(0xffffffffu, p0d, 1);
        p0d += __shfl_xor_sync(0xffffffffu, p0d, 2);
        p1s += __shfl_xor_sync(0xffffffffu, p1s, 1);
        p1s += __shfl_xor_sync(0xffffffffu, p1s, 2);
        p1d += __shfl_xor_sync(0xffffffffu, p1d, 1);
        p1d += __shfl_xor_sync(0xffffffffu, p1d, 2);
        if (q == 0) {
            if (r0 < Nn) { g_as1[(size_t)r0 * NH1 + nt] = p0s; g_ad1[(size_t)r0 * NH1 + nt] = p0d; }
            if (r1 < Nn) { g_as1[(size_t)r1 * NH1 + nt] = p1s; g_ad1[(size_t)r1 * NH1 + nt] = p1d; }
        }
    }
}

// ---------------------------------------------------------------------------
// layer-1 fused softmax+aggregate, single pass. One warp per node.
// ---------------------------------------------------------------------------
__global__ __launch_bounds__(256) void agg1_kernel(const float* __restrict__ bias1, int N) {
    int node = (blockIdx.x * blockDim.x + threadIdx.x) >> 5;
    int lane = threadIdx.x & 31;
    if (node >= N) return;
    int start = g_rowptr[node];
    int deg   = g_rowptr[node + 1] - start;
    int hl = lane & 7;
    int hh = lane >> 2;

    float adv   = g_ad1[(size_t)node * NH1 + hl];
    float selfe = __expf(lrelu(g_as1[(size_t)node * NH1 + hl] + adv));
    float2 hv = *(const float2*)&g_h1[(size_t)node * HID + 2 * lane];

    float ax = 0.f, ay = 0.f;
    float s = 0.f;
    for (int base = 0; base < deg; base += 4) {
        int idx = base + (lane >> 3);
        int j = 0; float wt = 0.f;
        if (idx < deg) {
            j = g_col[start + idx];
            wt = __expf(lrelu(g_as1[(size_t)j * NH1 + hl] + adv));
        }
        s += wt;
        int nb = min(4, deg - base);
        #pragma unroll
        for (int e = 0; e < 4; e++) {
            if (e >= nb) break;
            float we = __shfl_sync(0xffffffffu, wt, e * 8 + hh);
            int je   = __shfl_sync(0xffffffffu, j, e * 8);
            float2 v = *(const float2*)&g_h1[(size_t)je * HID + 2 * lane];
            ax = fmaf(we, v.x, ax);
            ay = fmaf(we, v.y, ay);
        }
    }
    s += __shfl_xor_sync(0xffffffffu, s, 8);
    s += __shfl_xor_sync(0xffffffffu, s, 16);
    s += selfe;
    float inv = 1.f / (s + EPSV);
    float invB   = __shfl_sync(0xffffffffu, inv, hh);
    float selfeB = __shfl_sync(0xffffffffu, selfe, hh);
    ax = (ax + selfeB * hv.x) * invB;
    ay = (ay + selfeB * hv.y) * invB;
    float2 bb = *(const float2*)&bias1[2 * lane];
    ax += bb.x; ay += bb.y;
    ax = ax > 0.f ? ax : (__expf(ax) - 1.f);
    ay = ay > 0.f ? ay : (__expf(ay) - 1.f);
    *(float2*)&g_helu[(size_t)node * HID + 2 * lane] = make_float2(ax, ay);
}

// ---------------------------------------------------------------------------
// layer-2 GEMM (thread per node) + attention scalars
// ---------------------------------------------------------------------------
__global__ __launch_bounds__(256) void gemm2_kernel(const float* __restrict__ W2,
                                                    const float* __restrict__ att_s,
                                                    const float* __restrict__ att_d,
                                                    int N) {
    __shared__ float sW[HID * C2];
    __shared__ float sas[C2], sad[C2];
    int tid = threadIdx.x;
    for (int i = tid; i < HID * C2; i += blockDim.x) sW[i] = W2[i];
    if (tid < C2) { sas[tid] = att_s[tid]; sad[tid] = att_d[tid]; }
    __syncthreads();
    int n = blockIdx.x * blockDim.x + tid;
    if (n >= N) return;
    float acc[C2];
    #pragma unroll
    for (int c = 0; c < C2; c++) acc[c] = 0.f;
    const float* hr = &g_helu[(size_t)n * HID];
    #pragma unroll
    for (int k = 0; k < HID; k += 4) {
        float4 h4 = *(const float4*)&hr[k];
        #pragma unroll
        for (int c = 0; c < C2; c++) {
            acc[c] = fmaf(h4.x, sW[(k + 0) * C2 + c], acc[c]);
            acc[c] = fmaf(h4.y, sW[(k + 1) * C2 + c], acc[c]);
            acc[c] = fmaf(h4.z, sW[(k + 2) * C2 + c], acc[c]);
            acc[c] = fmaf(h4.w, sW[(k + 3) * C2 + c], acc[c]);
        }
    }
    #pragma unroll
    for (int c = 0; c < C2; c += 4)
        *(float4*)&g_y2[(size_t)n * C2 + c] = make_float4(acc[c], acc[c+1], acc[c+2], acc[c+3]);
    float ps = 0.f, pd = 0.f;
    #pragma unroll
    for (int c = 0; c < C2; c++) { ps = fmaf(acc[c], sas[c], ps); pd = fmaf(acc[c], sad[c], pd); }
    g_as2[n] = ps;
    g_ad2[n] = pd;
}

// ---------------------------------------------------------------------------
// layer-2 fused softmax+aggregate, single pass + bias + final softmax
// ---------------------------------------------------------------------------
__global__ __launch_bounds__(256) void agg2_kernel(const float* __restrict__ bias2,
                                                   float* __restrict__ out, int N) {
    int node = (blockIdx.x * blockDim.x + threadIdx.x) >> 5;
    int lane = threadIdx.x & 31;
    if (node >= N) return;
    int start = g_rowptr[node];
    int deg   = g_rowptr[node + 1] - start;

    float ad    = g_ad2[node];
    float selfe = __expf(lrelu(g_as2[node] + ad));
    int c = lane & 15, half = lane >> 4;

    float acc = 0.f;
    float s = 0.f;
    for (int base = 0; base < deg; base += 32) {
        int idx = base + lane;
        int j = 0; float wt = 0.f;
        if (idx < deg) {
            j = g_col[start + idx];
            wt = __expf(lrelu(g_as2[j] + ad));
        }
        s += wt;
        int nb = min(32, deg - base);
        for (int p = 0; p < nb; p += 2) {
            int e = p + half;
            float we = __shfl_sync(0xffffffffu, wt, e & 31);
            int je   = __shfl_sync(0xffffffffu, j, e & 31);
            if (e < nb) acc = fmaf(we, g_y2[(size_t)je * C2 + c], acc);
        }
    }
    #pragma unroll
    for (int d = 16; d >= 1; d >>= 1)
        s += __shfl_xor_sync(0xffffffffu, s, d);
    s += selfe;
    float inv = 1.f / (s + EPSV);

    acc += __shfl_xor_sync(0xffffffffu, acc, 16);
    acc = (acc + selfe * g_y2[(size_t)node * C2 + c]) * inv;
    acc += bias2[c];

    float mx = acc;
    #pragma unroll
    for (int d = 8; d >= 1; d >>= 1)
        mx = fmaxf(mx, __shfl_xor_sync(0xffffffffu, mx, d));
    float p = __expf(acc - mx);
    float ss = p;
    #pragma unroll
    for (int d = 8; d >= 1; d >>= 1)
        ss += __shfl_xor_sync(0xffffffffu, ss, d);
    float soft = p / ss;

    if (lane < 16) {
        out[(size_t)node * C2 + c] = soft;
        out[(size_t)N * C2 + (size_t)node * C2 + c] = acc;
    }
}

// ---------------------------------------------------------------------------
// launch: CSR build (default stream) runs CONCURRENT with convW+gemm1 (s2).
// Fork/join via events — graph-capture legal, handles created once lazily.
// ---------------------------------------------------------------------------
extern "C" void kernel_launch(void* const* d_in, const int* in_sizes, int n_in,
                              void* d_out, int out_size) {
    const float* x   = (const float*)d_in[0];
    const void*  ei  = d_in[1];
    const float* W1  = (const float*)d_in[2];
    const float* as1 = (const float*)d_in[3];
    const float* ad1 = (const float*)d_in[4];
    const float* b1  = (const float*)d_in[5];
    const float* W2  = (const float*)d_in[6];
    const float* as2 = (const float*)d_in[7];
    const float* ad2 = (const float*)d_in[8];
    const float* b2  = (const float*)d_in[9];
    float* out = (float*)d_out;

    int E = in_sizes[1] / 2;
    int N = in_sizes[0] / FIN;
    int NB = (N + 1023) / 1024;

    static cudaStream_t s2 = nullptr;
    static cudaEvent_t evFork = nullptr, evJoin = nullptr;
    if (s2 == nullptr) {
        cudaStreamCreateWithFlags(&s2, cudaStreamNonBlocking);
        cudaEventCreateWithFlags(&evFork, cudaEventDisableTiming);
        cudaEventCreateWithFlags(&evJoin, cudaEventDisableTiming);
    }

    // fork: side stream runs the GEMM1 chain (independent of edge data)
    cudaEventRecord(evFork, 0);
    cudaStreamWaitEvent(s2, evFork, 0);
    convW_kernel<<<64, 256, 0, s2>>>(W1);
    gemm1_mma_kernel<<<(N + 127) / 128, 256, 0, s2>>>(x, as1, ad1, N);
    cudaEventRecord(evJoin, s2);

    // default stream: CSR build chain
    detect_kernel<<<1, 32>>>((const long long*)ei, N, E);
    zero_cnt_kernel<<<(N + 255) / 256, 256>>>(N);
    count_kernel<<<(E + 255) / 256, 256>>>(ei, E, N);
    scan1_kernel<<<NB, 1024>>>(N);
    scan2_kernel<<<1, 128>>>(NB, N);
    scan3_kernel<<<NB, 1024>>>(N);
    scatter_kernel<<<(E + 255) / 256, 256>>>(ei, E);

    // join: agg1 needs both CSR and h1/as1/ad1
    cudaStreamWaitEvent(0, evJoin, 0);
    agg1_kernel<<<(N + 7) / 8, 256>>>(b1, N);
    gemm2_kernel<<<(N + 255) / 256, 256>>>(W2, as2, ad2, N);
    agg2_kernel<<<(N + 7) / 8, 256>>>(b2, out, N);
}